// round 11
// baseline (speedup 1.0000x reference)
#include <cuda_runtime.h>
#include <cuda_bf16.h>
#include <cstdint>

// ---------------------------------------------------------------------------
// ArcFace, warp-MMA edition v4.1 (base sm_103: mma.sync + ldmatrix + cp.async).
//   prep:  fp32 rows -> (hi,lo) bf16 split + inverse norms (persistent)
//   gemm:  persistent-ish CTAs: BM=64 x BN=64, feat tile loaded ONCE,
//          W double-buffered with cp.async prefetch across the c-tile loop,
//          3-pass split-bf16 mma.sync, halved smem-staged coalesced epilogue,
//          gt margin patch fused.  2 CTAs/SM, single wave (296 CTAs).
//   v4.1 fix: IP_PITCH 66 -> 68 (staging rows must be 16B-aligned for LDS.128)
// ---------------------------------------------------------------------------

static __device__ __constant__ float kCOS_M  = 0.8775825618903728f;   // cos(0.5)
static __device__ __constant__ float kSIN_M  = 0.4794255386042030f;   // sin(0.5)
static __device__ __constant__ float kTHRESH = -0.8775825618903728f;  // -cos(0.5)
#define K_SCALE 35.0f

#define MAXB 1024
#define MAXC 100608
__device__ float g_invnf[MAXB];
__device__ float g_invnw[MAXC];
__device__ __nv_bfloat16 g_fhi[MAXB * 128];
__device__ __nv_bfloat16 g_flo[MAXB * 128];
__device__ __nv_bfloat16 g_whi[(size_t)MAXC * 128];
__device__ __nv_bfloat16 g_wlo[(size_t)MAXC * 128];

// ---------------------------------------------------------------------------
__device__ __forceinline__ uint32_t smem_u32(const void* p) {
    uint32_t a;
    asm("{ .reg .u64 t; cvta.to.shared.u64 t, %1; cvt.u32.u64 %0, t; }"
        : "=r"(a) : "l"(p));
    return a;
}
__device__ __forceinline__ void cp16(uint32_t dst, const void* src, uint32_t nbytes) {
    asm volatile("cp.async.cg.shared.global [%0], [%1], 16, %2;"
                 :: "r"(dst), "l"(src), "r"(nbytes));
}
__device__ __forceinline__ void cp_commit() {
    asm volatile("cp.async.commit_group;" ::: "memory");
}
__device__ __forceinline__ void cp_wait0() {
    asm volatile("cp.async.wait_group 0;" ::: "memory");
}
__device__ __forceinline__ void ldsm4(uint32_t* r, uint32_t addr) {
    asm volatile("ldmatrix.sync.aligned.m8n8.x4.shared.b16 {%0,%1,%2,%3}, [%4];"
                 : "=r"(r[0]), "=r"(r[1]), "=r"(r[2]), "=r"(r[3]) : "r"(addr));
}
__device__ __forceinline__ void mma16816(float* c, const uint32_t* a,
                                         uint32_t b0, uint32_t b1) {
    asm volatile(
        "mma.sync.aligned.m16n8k16.row.col.f32.bf16.bf16.f32 "
        "{%0,%1,%2,%3}, {%4,%5,%6,%7}, {%8,%9}, {%0,%1,%2,%3};"
        : "+f"(c[0]), "+f"(c[1]), "+f"(c[2]), "+f"(c[3])
        : "r"(a[0]), "r"(a[1]), "r"(a[2]), "r"(a[3]), "r"(b0), "r"(b1));
}
// tile row address: row r (256B rows), 16B chunk c (0..15), XOR swizzle
__device__ __forceinline__ uint32_t sw_row(uint32_t r, uint32_t c) {
    return r * 256u + ((c ^ (r & 7)) << 4);
}

// smem layout: f tiles 32KB, W double buffer 2x32KB, ip half-plane, aux
#define OF_FHI 0
#define OF_FLO 16384
#define OF_W0  32768            // whi=+0 (16KB), wlo=+16384
#define OF_IPS 98304            // 32 x 68 fp32 = 8704B
#define OF_INVF 107008          // 64 floats
#define OF_LAB  107264          // 64 ints
#define SMEM_TOTAL 107520
#define IP_PITCH 68             // 68*4 = 272B rows -> 16B-aligned float4

// ---------------------------------------------------------------------------
__global__ void prep_kernel(const float* __restrict__ x, int rows, int which) {
    int row = blockIdx.x * 8 + (threadIdx.x >> 5);
    if (row >= rows) return;
    int lane = threadIdx.x & 31;
    float4 v = *reinterpret_cast<const float4*>(x + (size_t)row * 128 + lane * 4);
    float s = v.x * v.x + v.y * v.y + v.z * v.z + v.w * v.w;
#pragma unroll
    for (int o = 16; o > 0; o >>= 1) s += __shfl_xor_sync(0xffffffffu, s, o);
    float inv = rsqrtf(s);
    if (lane == 0) { if (which) g_invnw[row] = inv; else g_invnf[row] = inv; }

    float f[4] = {v.x, v.y, v.z, v.w};
    uint32_t hi[2], lo[2];
#pragma unroll
    for (int q = 0; q < 2; ++q) {
        __nv_bfloat16 h0 = __float2bfloat16(f[2 * q]);
        __nv_bfloat16 h1 = __float2bfloat16(f[2 * q + 1]);
        __nv_bfloat16 l0 = __float2bfloat16(f[2 * q] - __bfloat162float(h0));
        __nv_bfloat16 l1 = __float2bfloat16(f[2 * q + 1] - __bfloat162float(h1));
        hi[q] = (uint32_t)__bfloat16_as_ushort(h0) |
                ((uint32_t)__bfloat16_as_ushort(h1) << 16);
        lo[q] = (uint32_t)__bfloat16_as_ushort(l0) |
                ((uint32_t)__bfloat16_as_ushort(l1) << 16);
    }
    __nv_bfloat16* dhi = which ? g_whi : g_fhi;
    __nv_bfloat16* dlo = which ? g_wlo : g_flo;
    reinterpret_cast<uint2*>(dhi + (size_t)row * 128)[lane] = make_uint2(hi[0], hi[1]);
    reinterpret_cast<uint2*>(dlo + (size_t)row * 128)[lane] = make_uint2(lo[0], lo[1]);
}

// ---------------------------------------------------------------------------
__global__ __launch_bounds__(256, 2)
void arcface_mma(const int* __restrict__ label, float* __restrict__ out,
                 int B, int C, int nct, int gy) {
    extern __shared__ __align__(1024) char smem[];
    const uint32_t sb = smem_u32(smem);
    float* ipS    = reinterpret_cast<float*>(smem + OF_IPS);
    float* invf_s = reinterpret_cast<float*>(smem + OF_INVF);
    int*   lab_s  = reinterpret_cast<int*>(smem + OF_LAB);

    const int tid  = threadIdx.x;
    const int wid  = tid >> 5;
    const int lane = tid & 31;
    const int wm   = wid & 1;       // 2 warp-rows x 32
    const int wn   = wid >> 1;      // 4 warp-cols x 16
    const int m0   = blockIdx.x * 64;

    // ---- W tile loader (hi+lo, 1024 chunks each tile) ----------------------
    auto loadW = [&](int buf, int cc0) {
        const uint32_t offH = OF_W0 + (uint32_t)buf * 32768u;
        const uint32_t offL = offH + 16384u;
#pragma unroll
        for (int i = 0; i < 4; ++i) {
            int idx = tid + 256 * i;               // 0..1023
            uint32_t row = (uint32_t)idx >> 4, ck = (uint32_t)idx & 15;
            uint32_t so = sw_row(row, ck);
            int gc = cc0 + (int)row;
            uint32_t ok = (gc < C) ? 16u : 0u;
            size_t gs = (gc < C) ? (size_t)gc : 0;
            cp16(sb + offH + so, reinterpret_cast<const char*>(g_whi) + gs * 256 + ck * 16, ok);
            cp16(sb + offL + so, reinterpret_cast<const char*>(g_wlo) + gs * 256 + ck * 16, ok);
        }
    };

    // ---- one-time fills: f tiles + aux + first W tile ----------------------
#pragma unroll
    for (int i = 0; i < 4; ++i) {
        int idx = tid + 256 * i;                   // 0..1023
        uint32_t row = (uint32_t)idx >> 4, ck = (uint32_t)idx & 15;
        uint32_t so = sw_row(row, ck);
        int gm = m0 + (int)row;
        uint32_t ok = (gm < B) ? 16u : 0u;
        size_t gs = (gm < B) ? (size_t)gm : 0;
        cp16(sb + OF_FHI + so, reinterpret_cast<const char*>(g_fhi) + gs * 256 + ck * 16, ok);
        cp16(sb + OF_FLO + so, reinterpret_cast<const char*>(g_flo) + gs * 256 + ck * 16, ok);
    }
    loadW(0, blockIdx.y * 64);
    if (tid < 64) {
        invf_s[tid] = (m0 + tid < B) ? g_invnf[m0 + tid] : 0.f;
        lab_s[tid]  = (m0 + tid < B) ? label[m0 + tid] : -1;
    }
    cp_commit();
    cp_wait0();
    __syncthreads();

    const uint32_t lrow = lane & 15, lhalf = lane >> 4;
    const uint32_t arow0 = (uint32_t)(wm * 32) + lrow;
    const uint32_t arow1 = arow0 + 16;
    const uint32_t brow  = (uint32_t)(wn * 16) + lrow;

    const size_t BC = (size_t)B * (size_t)C;
    float* __restrict__ outCos = out;
    float* __restrict__ outMrg = out + BC;
    float* __restrict__ outIp  = out + 2 * BC;
    const int lc4 = (lane & 15) * 4;
    const int lh  = lane >> 4;

    int cur = 0;
    for (int ct = blockIdx.y; ct < nct; ct += gy, cur ^= 1) {
        const int c0 = ct * 64;

        // prefetch next W tile into the other buffer (overlaps mma+epilogue)
        const int ctn = ct + gy;
        if (ctn < nct) { loadW(cur ^ 1, ctn * 64); cp_commit(); }

        // ---- mainloop: 3 passes x 8 k16-steps ------------------------------
        float acc[2][2][4];
#pragma unroll
        for (int mi = 0; mi < 2; ++mi)
#pragma unroll
            for (int ni = 0; ni < 2; ++ni)
#pragma unroll
                for (int q = 0; q < 4; ++q) acc[mi][ni][q] = 0.f;

        const uint32_t whOf = OF_W0 + (uint32_t)cur * 32768u;
        const uint32_t wlOf = whOf + 16384u;
        const uint32_t aOf[3] = {OF_FHI, OF_FHI, OF_FLO};
        const uint32_t bOf[3] = {whOf, wlOf, whOf};

#pragma unroll
        for (int pass = 0; pass < 3; ++pass) {
            const uint32_t ab = sb + aOf[pass];
            const uint32_t bb = sb + bOf[pass];
#pragma unroll
            for (int s = 0; s < 8; ++s) {
                const uint32_t ck = (uint32_t)(s * 2) + lhalf;
                uint32_t a[2][4], b[4];
                ldsm4(a[0], ab + sw_row(arow0, ck));
                ldsm4(a[1], ab + sw_row(arow1, ck));
                ldsm4(b, bb + sw_row(brow, ck));
#pragma unroll
                for (int mi = 0; mi < 2; ++mi) {
                    mma16816(acc[mi][0], a[mi], b[0], b[2]);
                    mma16816(acc[mi][1], a[mi], b[1], b[3]);
                }
            }
        }

        // ---- per-iteration invw (column norms) -----------------------------
        const int gc = c0 + lc4;
        float4 invw4;
        if (gc + 4 <= C) {
            invw4 = *reinterpret_cast<const float4*>(g_invnw + gc);
        } else {
            invw4 = make_float4(0.f, 0.f, 0.f, 0.f);
            for (int q = 0; q < 4; ++q)
                if (gc + q < C) (&invw4.x)[q] = g_invnw[gc + q];
        }

        // ---- epilogue in 32-row halves -------------------------------------
#pragma unroll
        for (int h = 0; h < 2; ++h) {
            __syncthreads();                    // ipS free (prev readers done)
            if (wm == h) {                      // stage this half's fragments
#pragma unroll
                for (int mi = 0; mi < 2; ++mi)
#pragma unroll
                    for (int hh = 0; hh < 2; ++hh) {
                        int r = mi * 16 + (lane >> 2) + hh * 8;
#pragma unroll
                        for (int ni = 0; ni < 2; ++ni) {
                            int cc = wn * 16 + ni * 8 + (lane & 3) * 2;
                            *reinterpret_cast<float2*>(&ipS[r * IP_PITCH + cc]) =
                                make_float2(acc[mi][ni][2 * hh], acc[mi][ni][2 * hh + 1]);
                        }
                    }
            }
            __syncthreads();
            // store 32 rows: warp -> 4 rows (2 iters x 2 rows)
#pragma unroll
            for (int it = 0; it < 2; ++it) {
                const int rl = wid * 4 + it * 2 + lh;
                const int m = m0 + h * 32 + rl;
                if (m >= B) continue;
                float4 ip = *reinterpret_cast<const float4*>(&ipS[rl * IP_PITCH + lc4]);
                const float invf = invf_s[h * 32 + rl];
                float4 cv = make_float4(ip.x * invf * invw4.x, ip.y * invf * invw4.y,
                                        ip.z * invf * invw4.z, ip.w * invf * invw4.w);
                float4 mv = make_float4(K_SCALE * cv.x, K_SCALE * cv.y,
                                        K_SCALE * cv.z, K_SCALE * cv.w);
                const int lab = lab_s[h * 32 + rl];
                if ((unsigned)(lab - gc) < 4u) {
                    float cg = (&cv.x)[lab - gc];
                    float cl = fminf(fmaxf(cg, -1.f), 1.f);
                    float val;
                    if (cg > kTHRESH) {
                        float s = sqrtf(fmaxf(1.f - cl * cl, 0.f));
                        val = cl * kCOS_M - s * kSIN_M;
                    } else {
                        val = cl - 0.5f * kSIN_M;
                    }
                    (&mv.x)[lab - gc] = K_SCALE * val;
                }
                const size_t ro = (size_t)m * (size_t)C;
                if (gc + 4 <= C) {
                    *reinterpret_cast<float4*>(outCos + ro + gc) = cv;
                    *reinterpret_cast<float4*>(outMrg + ro + gc) = mv;
                    *reinterpret_cast<float4*>(outIp  + ro + gc) = ip;
                } else if (gc < C) {
                    for (int q = 0; q < 4 && gc + q < C; ++q) {
                        outCos[ro + gc + q] = (&cv.x)[q];
                        outMrg[ro + gc + q] = (&mv.x)[q];
                        outIp [ro + gc + q] = (&ip.x)[q];
                    }
                }
            }
        }

        cp_wait0();                 // next W tile resident
        __syncthreads();
    }
}

// ---------------------------------------------------------------------------
extern "C" void kernel_launch(void* const* d_in, const int* in_sizes, int n_in,
                              void* d_out, int out_size) {
    const float* feat  = (const float*)d_in[0];
    const float* W     = (const float*)d_in[1];
    const int*   label = (const int*)d_in[2];
    const int D = 128;
    int B = in_sizes[0] / D;
    int C = in_sizes[1] / D;
    float* out = (float*)d_out;

    prep_kernel<<<(B + 7) / 8, 256>>>(feat, B, 0);
    prep_kernel<<<(C + 7) / 8, 256>>>(W, C, 1);

    int gx  = (B + 63) / 64;                       // m-tiles (4 for B=256)
    int nct = (C + 63) / 64;                       // c-tiles (1563)
    int gy  = 296 / (gx > 0 ? gx : 1);             // CTA columns (74) -> 2/SM
    if (gy < 1) gy = 1;
    if (gy > nct) gy = nct;

    cudaFuncSetAttribute(arcface_mma, cudaFuncAttributeMaxDynamicSharedMemorySize,
                         SMEM_TOTAL);
    dim3 grid(gx, gy);
    arcface_mma<<<grid, 256, SMEM_TOTAL>>>(label, out, B, C, nct, gy);
}

// round 15
// speedup vs baseline: 1.7360x; 1.7360x over previous
#include <cuda_runtime.h>
#include <cuda_bf16.h>
#include <cstdint>

// ---------------------------------------------------------------------------
// ArcFace, warp-MMA edition v5 (= v3 structure @150.1us + merged prep).
//   prep:  ONE kernel: fp32 rows of feat AND W -> (hi,lo) bf16 split + norms
//   gemm:  BM=128 x BN=64 tiles, 96KB smem -> 2 CTAs/SM, cp.async fills,
//          3-pass split-bf16 mma.sync, smem-staged coalesced epilogue,
//          gt margin patch fused.
//   Launch pattern is now [prep, gemm] so ncu -s 5 captures the GEMM.
// ---------------------------------------------------------------------------

static __device__ __constant__ float kCOS_M  = 0.8775825618903728f;   // cos(0.5)
static __device__ __constant__ float kSIN_M  = 0.4794255386042030f;   // sin(0.5)
static __device__ __constant__ float kTHRESH = -0.8775825618903728f;  // -cos(0.5)
#define K_SCALE 35.0f

#define MAXB 1024
#define MAXC 100608
__device__ float g_invnf[MAXB];
__device__ float g_invnw[MAXC];
__device__ __nv_bfloat16 g_fhi[MAXB * 128];
__device__ __nv_bfloat16 g_flo[MAXB * 128];
__device__ __nv_bfloat16 g_whi[(size_t)MAXC * 128];
__device__ __nv_bfloat16 g_wlo[(size_t)MAXC * 128];

// ---------------------------------------------------------------------------
__device__ __forceinline__ uint32_t smem_u32(const void* p) {
    uint32_t a;
    asm("{ .reg .u64 t; cvta.to.shared.u64 t, %1; cvt.u32.u64 %0, t; }"
        : "=r"(a) : "l"(p));
    return a;
}
__device__ __forceinline__ void cp16(uint32_t dst, const void* src, uint32_t nbytes) {
    asm volatile("cp.async.cg.shared.global [%0], [%1], 16, %2;"
                 :: "r"(dst), "l"(src), "r"(nbytes));
}
__device__ __forceinline__ void cp_wait_all() {
    asm volatile("cp.async.wait_all;" ::: "memory");
}
__device__ __forceinline__ void ldsm4(uint32_t* r, uint32_t addr) {
    asm volatile("ldmatrix.sync.aligned.m8n8.x4.shared.b16 {%0,%1,%2,%3}, [%4];"
                 : "=r"(r[0]), "=r"(r[1]), "=r"(r[2]), "=r"(r[3]) : "r"(addr));
}
__device__ __forceinline__ void mma16816(float* c, const uint32_t* a,
                                         uint32_t b0, uint32_t b1) {
    asm volatile(
        "mma.sync.aligned.m16n8k16.row.col.f32.bf16.bf16.f32 "
        "{%0,%1,%2,%3}, {%4,%5,%6,%7}, {%8,%9}, {%0,%1,%2,%3};"
        : "+f"(c[0]), "+f"(c[1]), "+f"(c[2]), "+f"(c[3])
        : "r"(a[0]), "r"(a[1]), "r"(a[2]), "r"(a[3]), "r"(b0), "r"(b1));
}
// tile row address: row r (256B rows), 16B chunk c (0..15), XOR swizzle
__device__ __forceinline__ uint32_t sw_row(uint32_t r, uint32_t c) {
    return r * 256u + ((c ^ (r & 7)) << 4);
}

// smem layout (96KB tiles + aux). ip plane reuses f region after mainloop.
#define OF_FHI 0
#define OF_FLO 32768
#define OF_WHI 65536
#define OF_WLO 81920
#define OF_INVW 98304           // 64 floats
#define OF_INVF 98560           // 128 floats
#define OF_LAB  99072           // 128 ints
#define SMEM_TOTAL 99584
#define IP_PITCH 68             // fp32 plane pitch (64 + 4 pad), 16B-aligned rows

// ---------------------------------------------------------------------------
// merged prep: rows [0,B) = feat, rows [B,B+C) = W
// ---------------------------------------------------------------------------
__global__ void prep_kernel(const float* __restrict__ feat,
                            const float* __restrict__ W, int B, int C) {
    int row = blockIdx.x * 8 + (threadIdx.x >> 5);
    int total = B + C;
    if (row >= total) return;
    int lane = threadIdx.x & 31;
    const bool isW = (row >= B);
    const float* x = isW ? W : feat;
    int r = isW ? (row - B) : row;

    float4 v = *reinterpret_cast<const float4*>(x + (size_t)r * 128 + lane * 4);
    float s = v.x * v.x + v.y * v.y + v.z * v.z + v.w * v.w;
#pragma unroll
    for (int o = 16; o > 0; o >>= 1) s += __shfl_xor_sync(0xffffffffu, s, o);
    float inv = rsqrtf(s);
    if (lane == 0) { if (isW) g_invnw[r] = inv; else g_invnf[r] = inv; }

    float f[4] = {v.x, v.y, v.z, v.w};
    uint32_t hi[2], lo[2];
#pragma unroll
    for (int q = 0; q < 2; ++q) {
        __nv_bfloat16 h0 = __float2bfloat16(f[2 * q]);
        __nv_bfloat16 h1 = __float2bfloat16(f[2 * q + 1]);
        __nv_bfloat16 l0 = __float2bfloat16(f[2 * q] - __bfloat162float(h0));
        __nv_bfloat16 l1 = __float2bfloat16(f[2 * q + 1] - __bfloat162float(h1));
        hi[q] = (uint32_t)__bfloat16_as_ushort(h0) |
                ((uint32_t)__bfloat16_as_ushort(h1) << 16);
        lo[q] = (uint32_t)__bfloat16_as_ushort(l0) |
                ((uint32_t)__bfloat16_as_ushort(l1) << 16);
    }
    __nv_bfloat16* dhi = isW ? g_whi : g_fhi;
    __nv_bfloat16* dlo = isW ? g_wlo : g_flo;
    reinterpret_cast<uint2*>(dhi + (size_t)r * 128)[lane] = make_uint2(hi[0], hi[1]);
    reinterpret_cast<uint2*>(dlo + (size_t)r * 128)[lane] = make_uint2(lo[0], lo[1]);
}

// ---------------------------------------------------------------------------
__global__ __launch_bounds__(256, 2)
void arcface_mma(const int* __restrict__ label, float* __restrict__ out,
                 int B, int C) {
    extern __shared__ __align__(1024) char smem[];
    const uint32_t sb = smem_u32(smem);
    float* invw_s = reinterpret_cast<float*>(smem + OF_INVW);
    float* invf_s = reinterpret_cast<float*>(smem + OF_INVF);
    int*   lab_s  = reinterpret_cast<int*>(smem + OF_LAB);

    const int tid  = threadIdx.x;
    const int wid  = tid >> 5;
    const int lane = tid & 31;
    const int wm   = wid & 3;       // 4 warp-rows x 32
    const int wn   = wid >> 2;      // 2 warp-cols x 32
    const int m0   = blockIdx.x * 128;   // m in grid.x: W-sharing CTAs adjacent
    const int c0   = blockIdx.y * 64;

    // ---- async tile fills (pre-split bf16 from prep kernel) ----------------
#pragma unroll
    for (int i = 0; i < 8; ++i) {                 // feat: 2048 chunks / tile pair
        int idx = tid + 256 * i;
        uint32_t row = (uint32_t)idx >> 4, ck = (uint32_t)idx & 15;
        uint32_t so = sw_row(row, ck);
        int gm = m0 + (int)row;
        uint32_t ok = (gm < B) ? 16u : 0u;
        size_t gs = (gm < B) ? (size_t)gm : 0;
        cp16(sb + OF_FHI + so, reinterpret_cast<const char*>(g_fhi) + gs * 256 + ck * 16, ok);
        cp16(sb + OF_FLO + so, reinterpret_cast<const char*>(g_flo) + gs * 256 + ck * 16, ok);
    }
#pragma unroll
    for (int i = 0; i < 4; ++i) {                 // W: 1024 chunks / tile pair
        int idx = tid + 256 * i;
        uint32_t row = (uint32_t)idx >> 4, ck = (uint32_t)idx & 15;
        uint32_t so = sw_row(row, ck);
        int gc = c0 + (int)row;
        uint32_t ok = (gc < C) ? 16u : 0u;
        size_t gs = (gc < C) ? (size_t)gc : 0;
        cp16(sb + OF_WHI + so, reinterpret_cast<const char*>(g_whi) + gs * 256 + ck * 16, ok);
        cp16(sb + OF_WLO + so, reinterpret_cast<const char*>(g_wlo) + gs * 256 + ck * 16, ok);
    }
    if (tid < 64)       invw_s[tid] = (c0 + tid < C) ? g_invnw[c0 + tid] : 0.f;
    else if (tid < 192) invf_s[tid - 64] = (m0 + tid - 64 < B) ? g_invnf[m0 + tid - 64] : 0.f;
    if (tid >= 128 && tid < 256) lab_s[tid - 128] = (m0 + tid - 128 < B) ? label[m0 + tid - 128] : -1;
    cp_wait_all();
    __syncthreads();

    // ---- mainloop: 3 passes x 8 k16-steps ----------------------------------
    float acc[2][4][4];
#pragma unroll
    for (int mi = 0; mi < 2; ++mi)
#pragma unroll
        for (int ni = 0; ni < 4; ++ni)
#pragma unroll
            for (int q = 0; q < 4; ++q) acc[mi][ni][q] = 0.f;

    const uint32_t lrow = lane & 15, lhalf = lane >> 4;
    const uint32_t arow0 = (uint32_t)(wm * 32) + lrow;
    const uint32_t arow1 = arow0 + 16;
    const uint32_t brow0 = (uint32_t)(wn * 32) + lrow;

    const uint32_t aOf[3] = {OF_FHI, OF_FHI, OF_FLO};
    const uint32_t bOf[3] = {OF_WHI, OF_WLO, OF_WHI};

#pragma unroll
    for (int pass = 0; pass < 3; ++pass) {
        const uint32_t ab = sb + aOf[pass];
        const uint32_t bb = sb + bOf[pass];
#pragma unroll
        for (int s = 0; s < 8; ++s) {
            const uint32_t ck = (uint32_t)(s * 2) + lhalf;
            uint32_t a[2][4], b[2][4];
            ldsm4(a[0], ab + sw_row(arow0, ck));
            ldsm4(a[1], ab + sw_row(arow1, ck));
            ldsm4(b[0], bb + sw_row(brow0, ck));
            ldsm4(b[1], bb + sw_row(brow0 + 16, ck));
#pragma unroll
            for (int mi = 0; mi < 2; ++mi)
#pragma unroll
                for (int ni = 0; ni < 4; ++ni) {
                    const int np = ni >> 1, od = ni & 1;
                    mma16816(acc[mi][ni], a[mi], b[np][od], b[np][od + 2]);
                }
        }
    }

    // ---- stage ip plane to smem (reuse f-tile region) ----------------------
    __syncthreads();
    float* ipS = reinterpret_cast<float*>(smem);
#pragma unroll
    for (int mi = 0; mi < 2; ++mi)
#pragma unroll
        for (int h = 0; h < 2; ++h) {
            int r = wm * 32 + mi * 16 + (lane >> 2) + h * 8;
#pragma unroll
            for (int ni = 0; ni < 4; ++ni) {
                int cc = wn * 32 + ni * 8 + (lane & 3) * 2;
                *reinterpret_cast<float2*>(&ipS[r * IP_PITCH + cc]) =
                    make_float2(acc[mi][ni][2 * h], acc[mi][ni][2 * h + 1]);
            }
        }
    __syncthreads();

    // ---- coalesced write-out: warp -> 2 rows/iter, 16 lanes x float4 -------
    const size_t BC = (size_t)B * (size_t)C;
    float* __restrict__ outCos = out;
    float* __restrict__ outMrg = out + BC;
    float* __restrict__ outIp  = out + 2 * BC;
    const int lh  = lane >> 4;              // row half
    const int lc4 = (lane & 15) * 4;        // column (0..60)
    const int gc  = c0 + lc4;
    const float4 invw4 = (gc + 4 <= C)
        ? *reinterpret_cast<const float4*>(&invw_s[lc4])
        : make_float4(0.f, 0.f, 0.f, 0.f);

#pragma unroll
    for (int it = 0; it < 8; ++it) {
        const int r = it * 16 + wid * 2 + lh;
        const int m = m0 + r;
        if (m >= B) continue;
        float4 ip = *reinterpret_cast<const float4*>(&ipS[r * IP_PITCH + lc4]);
        const float invf = invf_s[r];
        float4 cv = make_float4(ip.x * invf * invw4.x, ip.y * invf * invw4.y,
                                ip.z * invf * invw4.z, ip.w * invf * invw4.w);
        float4 mv = make_float4(K_SCALE * cv.x, K_SCALE * cv.y,
                                K_SCALE * cv.z, K_SCALE * cv.w);
        const int lab = lab_s[r];
        if ((unsigned)(lab - gc) < 4u) {
            float cg = (&cv.x)[lab - gc];
            float cl = fminf(fmaxf(cg, -1.f), 1.f);
            float val;
            if (cg > kTHRESH) {
                float s = sqrtf(fmaxf(1.f - cl * cl, 0.f));
                val = cl * kCOS_M - s * kSIN_M;
            } else {
                val = cl - 0.5f * kSIN_M;
            }
            (&mv.x)[lab - gc] = K_SCALE * val;
        }
        const size_t ro = (size_t)m * (size_t)C;
        if (gc + 4 <= C) {
            *reinterpret_cast<float4*>(outCos + ro + gc) = cv;
            *reinterpret_cast<float4*>(outMrg + ro + gc) = mv;
            *reinterpret_cast<float4*>(outIp  + ro + gc) = ip;
        } else if (gc < C) {
            for (int q = 0; q < 4 && gc + q < C; ++q) {
                outCos[ro + gc + q] = (&cv.x)[q];
                outMrg[ro + gc + q] = (&mv.x)[q];
                outIp [ro + gc + q] = (&ip.x)[q];
            }
        }
    }
}

// ---------------------------------------------------------------------------
extern "C" void kernel_launch(void* const* d_in, const int* in_sizes, int n_in,
                              void* d_out, int out_size) {
    const float* feat  = (const float*)d_in[0];
    const float* W     = (const float*)d_in[1];
    const int*   label = (const int*)d_in[2];
    const int D = 128;
    int B = in_sizes[0] / D;
    int C = in_sizes[1] / D;
    float* out = (float*)d_out;

    prep_kernel<<<(B + C + 7) / 8, 256>>>(feat, W, B, C);

    cudaFuncSetAttribute(arcface_mma, cudaFuncAttributeMaxDynamicSharedMemorySize,
                         SMEM_TOTAL);
    dim3 grid((B + 127) / 128, (C + 63) / 64);   // m in x -> W-sharing CTAs adjacent
    arcface_mma<<<grid, 256, SMEM_TOTAL>>>(label, out, B, C);
}

// round 16
// speedup vs baseline: 2.0903x; 1.2041x over previous
#include <cuda_runtime.h>
#include <cuda_bf16.h>
#include <cstdint>

// ---------------------------------------------------------------------------
// ArcFace, warp-MMA edition v6 (= v5 @145.6us with fused 3-in-1 mainloop).
//   prep:  ONE kernel: fp32 rows of feat AND W -> (hi,lo) bf16 split + norms
//   gemm:  BM=128 x BN=64 tiles, 96KB smem -> 2 CTAs/SM, cp.async fills,
//          SINGLE k-loop issuing hi*hi + hi*lo + lo*hi into one accumulator
//          (cuts LDSM traffic 33% vs 3 sequential passes), smem-staged
//          coalesced epilogue, gt margin patch fused.
// ---------------------------------------------------------------------------

static __device__ __constant__ float kCOS_M  = 0.8775825618903728f;   // cos(0.5)
static __device__ __constant__ float kSIN_M  = 0.4794255386042030f;   // sin(0.5)
static __device__ __constant__ float kTHRESH = -0.8775825618903728f;  // -cos(0.5)
#define K_SCALE 35.0f

#define MAXB 1024
#define MAXC 100608
__device__ float g_invnf[MAXB];
__device__ float g_invnw[MAXC];
__device__ __nv_bfloat16 g_fhi[MAXB * 128];
__device__ __nv_bfloat16 g_flo[MAXB * 128];
__device__ __nv_bfloat16 g_whi[(size_t)MAXC * 128];
__device__ __nv_bfloat16 g_wlo[(size_t)MAXC * 128];

// ---------------------------------------------------------------------------
__device__ __forceinline__ uint32_t smem_u32(const void* p) {
    uint32_t a;
    asm("{ .reg .u64 t; cvta.to.shared.u64 t, %1; cvt.u32.u64 %0, t; }"
        : "=r"(a) : "l"(p));
    return a;
}
__device__ __forceinline__ void cp16(uint32_t dst, const void* src, uint32_t nbytes) {
    asm volatile("cp.async.cg.shared.global [%0], [%1], 16, %2;"
                 :: "r"(dst), "l"(src), "r"(nbytes));
}
__device__ __forceinline__ void cp_wait_all() {
    asm volatile("cp.async.wait_all;" ::: "memory");
}
__device__ __forceinline__ void ldsm4(uint32_t* r, uint32_t addr) {
    asm volatile("ldmatrix.sync.aligned.m8n8.x4.shared.b16 {%0,%1,%2,%3}, [%4];"
                 : "=r"(r[0]), "=r"(r[1]), "=r"(r[2]), "=r"(r[3]) : "r"(addr));
}
__device__ __forceinline__ void mma16816(float* c, const uint32_t* a,
                                         uint32_t b0, uint32_t b1) {
    asm volatile(
        "mma.sync.aligned.m16n8k16.row.col.f32.bf16.bf16.f32 "
        "{%0,%1,%2,%3}, {%4,%5,%6,%7}, {%8,%9}, {%0,%1,%2,%3};"
        : "+f"(c[0]), "+f"(c[1]), "+f"(c[2]), "+f"(c[3])
        : "r"(a[0]), "r"(a[1]), "r"(a[2]), "r"(a[3]), "r"(b0), "r"(b1));
}
// tile row address: row r (256B rows), 16B chunk c (0..15), XOR swizzle
__device__ __forceinline__ uint32_t sw_row(uint32_t r, uint32_t c) {
    return r * 256u + ((c ^ (r & 7)) << 4);
}

// smem layout (96KB tiles + aux). ip plane reuses f region after mainloop.
#define OF_FHI 0
#define OF_FLO 32768
#define OF_WHI 65536
#define OF_WLO 81920
#define OF_INVW 98304           // 64 floats
#define OF_INVF 98560           // 128 floats
#define OF_LAB  99072           // 128 ints
#define SMEM_TOTAL 99584
#define IP_PITCH 68             // fp32 plane pitch (64 + 4 pad), 16B-aligned rows

// ---------------------------------------------------------------------------
// merged prep: rows [0,B) = feat, rows [B,B+C) = W
// ---------------------------------------------------------------------------
__global__ void prep_kernel(const float* __restrict__ feat,
                            const float* __restrict__ W, int B, int C) {
    int row = blockIdx.x * 8 + (threadIdx.x >> 5);
    int total = B + C;
    if (row >= total) return;
    int lane = threadIdx.x & 31;
    const bool isW = (row >= B);
    const float* x = isW ? W : feat;
    int r = isW ? (row - B) : row;

    float4 v = *reinterpret_cast<const float4*>(x + (size_t)r * 128 + lane * 4);
    float s = v.x * v.x + v.y * v.y + v.z * v.z + v.w * v.w;
#pragma unroll
    for (int o = 16; o > 0; o >>= 1) s += __shfl_xor_sync(0xffffffffu, s, o);
    float inv = rsqrtf(s);
    if (lane == 0) { if (isW) g_invnw[r] = inv; else g_invnf[r] = inv; }

    float f[4] = {v.x, v.y, v.z, v.w};
    uint32_t hi[2], lo[2];
#pragma unroll
    for (int q = 0; q < 2; ++q) {
        __nv_bfloat16 h0 = __float2bfloat16(f[2 * q]);
        __nv_bfloat16 h1 = __float2bfloat16(f[2 * q + 1]);
        __nv_bfloat16 l0 = __float2bfloat16(f[2 * q] - __bfloat162float(h0));
        __nv_bfloat16 l1 = __float2bfloat16(f[2 * q + 1] - __bfloat162float(h1));
        hi[q] = (uint32_t)__bfloat16_as_ushort(h0) |
                ((uint32_t)__bfloat16_as_ushort(h1) << 16);
        lo[q] = (uint32_t)__bfloat16_as_ushort(l0) |
                ((uint32_t)__bfloat16_as_ushort(l1) << 16);
    }
    __nv_bfloat16* dhi = isW ? g_whi : g_fhi;
    __nv_bfloat16* dlo = isW ? g_wlo : g_flo;
    reinterpret_cast<uint2*>(dhi + (size_t)r * 128)[lane] = make_uint2(hi[0], hi[1]);
    reinterpret_cast<uint2*>(dlo + (size_t)r * 128)[lane] = make_uint2(lo[0], lo[1]);
}

// ---------------------------------------------------------------------------
__global__ __launch_bounds__(256, 2)
void arcface_mma(const int* __restrict__ label, float* __restrict__ out,
                 int B, int C) {
    extern __shared__ __align__(1024) char smem[];
    const uint32_t sb = smem_u32(smem);
    float* invw_s = reinterpret_cast<float*>(smem + OF_INVW);
    float* invf_s = reinterpret_cast<float*>(smem + OF_INVF);
    int*   lab_s  = reinterpret_cast<int*>(smem + OF_LAB);

    const int tid  = threadIdx.x;
    const int wid  = tid >> 5;
    const int lane = tid & 31;
    const int wm   = wid & 3;       // 4 warp-rows x 32
    const int wn   = wid >> 2;      // 2 warp-cols x 32
    const int m0   = blockIdx.x * 128;   // m in grid.x: W-sharing CTAs adjacent
    const int c0   = blockIdx.y * 64;

    // ---- async tile fills (pre-split bf16 from prep kernel) ----------------
#pragma unroll
    for (int i = 0; i < 8; ++i) {                 // feat: 2048 chunks / tile pair
        int idx = tid + 256 * i;
        uint32_t row = (uint32_t)idx >> 4, ck = (uint32_t)idx & 15;
        uint32_t so = sw_row(row, ck);
        int gm = m0 + (int)row;
        uint32_t ok = (gm < B) ? 16u : 0u;
        size_t gs = (gm < B) ? (size_t)gm : 0;
        cp16(sb + OF_FHI + so, reinterpret_cast<const char*>(g_fhi) + gs * 256 + ck * 16, ok);
        cp16(sb + OF_FLO + so, reinterpret_cast<const char*>(g_flo) + gs * 256 + ck * 16, ok);
    }
#pragma unroll
    for (int i = 0; i < 4; ++i) {                 // W: 1024 chunks / tile pair
        int idx = tid + 256 * i;
        uint32_t row = (uint32_t)idx >> 4, ck = (uint32_t)idx & 15;
        uint32_t so = sw_row(row, ck);
        int gc = c0 + (int)row;
        uint32_t ok = (gc < C) ? 16u : 0u;
        size_t gs = (gc < C) ? (size_t)gc : 0;
        cp16(sb + OF_WHI + so, reinterpret_cast<const char*>(g_whi) + gs * 256 + ck * 16, ok);
        cp16(sb + OF_WLO + so, reinterpret_cast<const char*>(g_wlo) + gs * 256 + ck * 16, ok);
    }
    if (tid < 64)       invw_s[tid] = (c0 + tid < C) ? g_invnw[c0 + tid] : 0.f;
    else if (tid < 192) invf_s[tid - 64] = (m0 + tid - 64 < B) ? g_invnf[m0 + tid - 64] : 0.f;
    if (tid >= 128 && tid < 256) lab_s[tid - 128] = (m0 + tid - 128 < B) ? label[m0 + tid - 128] : -1;
    cp_wait_all();
    __syncthreads();

    // ---- fused mainloop: 8 k16-steps, 3 products each into one acc ---------
    float acc[2][4][4];
#pragma unroll
    for (int mi = 0; mi < 2; ++mi)
#pragma unroll
        for (int ni = 0; ni < 4; ++ni)
#pragma unroll
            for (int q = 0; q < 4; ++q) acc[mi][ni][q] = 0.f;

    const uint32_t lrow = lane & 15, lhalf = lane >> 4;
    const uint32_t arow0 = (uint32_t)(wm * 32) + lrow;
    const uint32_t arow1 = arow0 + 16;
    const uint32_t brow0 = (uint32_t)(wn * 32) + lrow;

#pragma unroll
    for (int s = 0; s < 8; ++s) {
        const uint32_t ck = (uint32_t)(s * 2) + lhalf;
        const uint32_t roA0 = sw_row(arow0, ck), roA1 = sw_row(arow1, ck);
        const uint32_t roB0 = sw_row(brow0, ck), roB1 = sw_row(brow0 + 16, ck);

        uint32_t ah[2][4], bh[2][4];
        ldsm4(ah[0], sb + OF_FHI + roA0);
        ldsm4(ah[1], sb + OF_FHI + roA1);
        ldsm4(bh[0], sb + OF_WHI + roB0);
        ldsm4(bh[1], sb + OF_WHI + roB1);
        // f_hi * w_hi
#pragma unroll
        for (int mi = 0; mi < 2; ++mi)
#pragma unroll
            for (int ni = 0; ni < 4; ++ni) {
                const int np = ni >> 1, od = ni & 1;
                mma16816(acc[mi][ni], ah[mi], bh[np][od], bh[np][od + 2]);
            }
        // f_hi * w_lo (reuses ah)
        {
            uint32_t bl[2][4];
            ldsm4(bl[0], sb + OF_WLO + roB0);
            ldsm4(bl[1], sb + OF_WLO + roB1);
#pragma unroll
            for (int mi = 0; mi < 2; ++mi)
#pragma unroll
                for (int ni = 0; ni < 4; ++ni) {
                    const int np = ni >> 1, od = ni & 1;
                    mma16816(acc[mi][ni], ah[mi], bl[np][od], bl[np][od + 2]);
                }
        }
        // f_lo * w_hi (reuses bh)
        {
            uint32_t al[2][4];
            ldsm4(al[0], sb + OF_FLO + roA0);
            ldsm4(al[1], sb + OF_FLO + roA1);
#pragma unroll
            for (int mi = 0; mi < 2; ++mi)
#pragma unroll
                for (int ni = 0; ni < 4; ++ni) {
                    const int np = ni >> 1, od = ni & 1;
                    mma16816(acc[mi][ni], al[mi], bh[np][od], bh[np][od + 2]);
                }
        }
    }

    // ---- stage ip plane to smem (reuse f-tile region) ----------------------
    __syncthreads();
    float* ipS = reinterpret_cast<float*>(smem);
#pragma unroll
    for (int mi = 0; mi < 2; ++mi)
#pragma unroll
        for (int h = 0; h < 2; ++h) {
            int r = wm * 32 + mi * 16 + (lane >> 2) + h * 8;
#pragma unroll
            for (int ni = 0; ni < 4; ++ni) {
                int cc = wn * 32 + ni * 8 + (lane & 3) * 2;
                *reinterpret_cast<float2*>(&ipS[r * IP_PITCH + cc]) =
                    make_float2(acc[mi][ni][2 * h], acc[mi][ni][2 * h + 1]);
            }
        }
    __syncthreads();

    // ---- coalesced write-out: warp -> 2 rows/iter, 16 lanes x float4 -------
    const size_t BC = (size_t)B * (size_t)C;
    float* __restrict__ outCos = out;
    float* __restrict__ outMrg = out + BC;
    float* __restrict__ outIp  = out + 2 * BC;
    const int lh  = lane >> 4;              // row half
    const int lc4 = (lane & 15) * 4;        // column (0..60)
    const int gc  = c0 + lc4;
    const float4 invw4 = (gc + 4 <= C)
        ? *reinterpret_cast<const float4*>(&invw_s[lc4])
        : make_float4(0.f, 0.f, 0.f, 0.f);

#pragma unroll
    for (int it = 0; it < 8; ++it) {
        const int r = it * 16 + wid * 2 + lh;
        const int m = m0 + r;
        if (m >= B) continue;
        float4 ip = *reinterpret_cast<const float4*>(&ipS[r * IP_PITCH + lc4]);
        const float invf = invf_s[r];
        float4 cv = make_float4(ip.x * invf * invw4.x, ip.y * invf * invw4.y,
                                ip.z * invf * invw4.z, ip.w * invf * invw4.w);
        float4 mv = make_float4(K_SCALE * cv.x, K_SCALE * cv.y,
                                K_SCALE * cv.z, K_SCALE * cv.w);
        const int lab = lab_s[r];
        if ((unsigned)(lab - gc) < 4u) {
            float cg = (&cv.x)[lab - gc];
            float cl = fminf(fmaxf(cg, -1.f), 1.f);
            float val;
            if (cg > kTHRESH) {
                float s = sqrtf(fmaxf(1.f - cl * cl, 0.f));
                val = cl * kCOS_M - s * kSIN_M;
            } else {
                val = cl - 0.5f * kSIN_M;
            }
            (&mv.x)[lab - gc] = K_SCALE * val;
        }
        const size_t ro = (size_t)m * (size_t)C;
        if (gc + 4 <= C) {
            *reinterpret_cast<float4*>(outCos + ro + gc) = cv;
            *reinterpret_cast<float4*>(outMrg + ro + gc) = mv;
            *reinterpret_cast<float4*>(outIp  + ro + gc) = ip;
        } else if (gc < C) {
            for (int q = 0; q < 4 && gc + q < C; ++q) {
                outCos[ro + gc + q] = (&cv.x)[q];
                outMrg[ro + gc + q] = (&mv.x)[q];
                outIp [ro + gc + q] = (&ip.x)[q];
            }
        }
    }
}

// ---------------------------------------------------------------------------
extern "C" void kernel_launch(void* const* d_in, const int* in_sizes, int n_in,
                              void* d_out, int out_size) {
    const float* feat  = (const float*)d_in[0];
    const float* W     = (const float*)d_in[1];
    const int*   label = (const int*)d_in[2];
    const int D = 128;
    int B = in_sizes[0] / D;
    int C = in_sizes[1] / D;
    float* out = (float*)d_out;

    prep_kernel<<<(B + C + 7) / 8, 256>>>(feat, W, B, C);

    cudaFuncSetAttribute(arcface_mma, cudaFuncAttributeMaxDynamicSharedMemorySize,
                         SMEM_TOTAL);
    dim3 grid((B + 127) / 128, (C + 63) / 64);   // m in x -> W-sharing CTAs adjacent
    arcface_mma<<<grid, 256, SMEM_TOTAL>>>(label, out, B, C);
}